// round 15
// baseline (speedup 1.0000x reference)
#include <cuda_runtime.h>
#include <cuda_bf16.h>
#include <cuda_fp16.h>
#include <math.h>
#include <cstdint>

// Problem constants
constexpr int B  = 4;
constexpr int S  = 2048;
constexpr int D  = 2048;
constexpr int H  = 16;
constexpr int DH = 128;
constexpr int M  = B * S;          // 8192 rows

// ---------------------------------------------------------------------------
// Scratch (allocation-free rule: device globals). fp16 everywhere.
// ---------------------------------------------------------------------------
__device__ __half g_x16[(size_t)M * D];
__device__ __half g_q16[(size_t)M * D];
__device__ __half g_k16[(size_t)M * D];
__device__ __half g_v16[(size_t)M * D];
__device__ __half g_c16[(size_t)M * D];
__device__ __half g_wT16[(size_t)4 * D * D];   // [w][N][K] single fp16

// ---------------------------------------------------------------------------
// PTX helpers (sm_103 baseline: mma.sync + ldmatrix + cp.async only)
// ---------------------------------------------------------------------------
__device__ __forceinline__ uint32_t smem_u32(const void* p) {
    uint32_t a;
    asm("{ .reg .u64 t; cvta.to.shared.u64 t, %1; cvt.u32.u64 %0, t; }" : "=r"(a) : "l"(p));
    return a;
}

__device__ __forceinline__ void cp_async16(uint32_t dst, const void* src) {
    asm volatile("cp.async.cg.shared.global [%0], [%1], 16;" :: "r"(dst), "l"(src));
}
#define CP_COMMIT() asm volatile("cp.async.commit_group;" ::: "memory")
#define CP_WAIT0()  asm volatile("cp.async.wait_group 0;" ::: "memory")
#define CP_WAIT1()  asm volatile("cp.async.wait_group 1;" ::: "memory")

__device__ __forceinline__ void ldsm_x4(uint32_t* r, uint32_t addr) {
    asm volatile("ldmatrix.sync.aligned.m8n8.x4.shared.b16 {%0,%1,%2,%3}, [%4];"
        : "=r"(r[0]), "=r"(r[1]), "=r"(r[2]), "=r"(r[3]) : "r"(addr));
}
__device__ __forceinline__ void ldsm_x4_t(uint32_t* r, uint32_t addr) {
    asm volatile("ldmatrix.sync.aligned.m8n8.x4.trans.shared.b16 {%0,%1,%2,%3}, [%4];"
        : "=r"(r[0]), "=r"(r[1]), "=r"(r[2]), "=r"(r[3]) : "r"(addr));
}

__device__ __forceinline__ void mma16816h(float* c, const uint32_t* a, const uint32_t* b) {
    asm volatile("mma.sync.aligned.m16n8k16.row.col.f32.f16.f16.f32 "
        "{%0,%1,%2,%3}, {%4,%5,%6,%7}, {%8,%9}, {%0,%1,%2,%3};"
        : "+f"(c[0]), "+f"(c[1]), "+f"(c[2]), "+f"(c[3])
        : "r"(a[0]), "r"(a[1]), "r"(a[2]), "r"(a[3]), "r"(b[0]), "r"(b[1]));
}

__device__ __forceinline__ uint32_t pack_f16(__half lo, __half hi) {
    __half2 h2 = __halves2half2(lo, hi);
    return *(uint32_t*)&h2;
}

// 2^z on the MUFU pipe (1 instruction; flushes large-negative to 0).
__device__ __forceinline__ float exp2_mufu(float z) {
    float r;
    asm("ex2.approx.f32 %0, %1;" : "=f"(r) : "f"(z));
    return r;
}

// ---------------------------------------------------------------------------
// Conversion kernels
// ---------------------------------------------------------------------------
__global__ __launch_bounds__(256) void conv_x_kernel(const float4* __restrict__ in) {
    size_t i = (size_t)blockIdx.x * blockDim.x + threadIdx.x;
    float4 v = in[i];
    __half h[4] = {__float2half_rn(v.x), __float2half_rn(v.y),
                   __float2half_rn(v.z), __float2half_rn(v.w)};
    *(uint2*)(g_x16 + i * 4) = *(const uint2*)h;
}

// Weights: W [K][N] fp32 -> transposed single fp16 [N][K]
__global__ __launch_bounds__(256) void wsplit_kernel(const float* __restrict__ Wq,
                                                     const float* __restrict__ Wk,
                                                     const float* __restrict__ Wv,
                                                     const float* __restrict__ Wo) {
    __shared__ float tile[32][33];
    int z = blockIdx.z;
    const float* W = (z == 0) ? Wq : (z == 1) ? Wk : (z == 2) ? Wv : Wo;
    __half* oh = g_wT16 + (size_t)z * D * D;
    int n0 = blockIdx.x * 32, k0 = blockIdx.y * 32;
    int tx = threadIdx.x & 31, ty = threadIdx.x >> 5;
    #pragma unroll
    for (int i = 0; i < 4; i++) {
        int k = ty + i * 8;
        tile[k][tx] = W[(size_t)(k0 + k) * D + n0 + tx];
    }
    __syncthreads();
    #pragma unroll
    for (int i = 0; i < 4; i++) {
        int n = ty + i * 8;
        oh[(size_t)(n0 + n) * D + k0 + tx] = __float2half_rn(tile[tx][n]);
    }
}

// ---------------------------------------------------------------------------
// mma.sync fp16 1-pass GEMM: C[TM x 128] = A @ B^T + bias
// TM=128: 4 warps 2x2, warp tile 64x64. TM=64: warp tile 32x64 (wave-fill).
// BK=32, 3-stage cp.async, ONE sync/iter. MODE: 0 = fp32 out, 2 = fp16 out.
// ---------------------------------------------------------------------------
constexpr int BKG      = 32;
constexpr int LDT      = 40;                 // f16 stride per tile row (80 B)
constexpr int B_TILE_BY = 128 * LDT * 2;     // 10240 B (B tile always 128 rows)
constexpr int NITER    = D / BKG;            // 64
constexpr int GEMM_SMEM_128 = 3 * (128 * LDT * 2 + B_TILE_BY);  // 61440 B
constexpr int GEMM_SMEM_64  = 3 * (64 * LDT * 2 + B_TILE_BY);   // 46080 B

template <int TM>
__device__ __forceinline__ void load_stage(uint32_t sbase,
                                           const __half* A,
                                           const __half* Bm,
                                           int k0, int t) {
    constexpr int A_TILE = TM * LDT * 2;
    #pragma unroll
    for (int i = 0; i < TM / 32; i++) {       // A: TM rows
        int idx  = t + 128 * i;
        int row  = idx >> 2;
        int chnk = idx & 3;
        cp_async16(sbase + row * (LDT * 2) + chnk * 16,
                   A + (size_t)row * D + k0 + chnk * 8);
    }
    #pragma unroll
    for (int i = 0; i < 4; i++) {             // B: 128 rows
        int idx  = t + 128 * i;
        int row  = idx >> 2;
        int chnk = idx & 3;
        cp_async16(sbase + A_TILE + row * (LDT * 2) + chnk * 16,
                   Bm + (size_t)row * D + k0 + chnk * 8);
    }
    CP_COMMIT();
}

template <int TM, int MODE>
__device__ __forceinline__ void tc_gemm_body(const __half* __restrict__ Ap,
                                             const __half* __restrict__ Bp,
                                             const float* __restrict__ bias,
                                             float* __restrict__ C,
                                             __half* __restrict__ F) {
    constexpr int A_TILE = TM * LDT * 2;
    constexpr int STAGE  = A_TILE + B_TILE_BY;
    constexpr int MF     = TM / 32;           // m-frags per warp
    extern __shared__ char smem[];
    const uint32_t sb = smem_u32(smem);
    const int t    = threadIdx.x;
    const int lane = t & 31;
    const int w    = t >> 5;
    const int wm   = (w & 1) * (TM / 2);
    const int wn   = (w >> 1) * 64;
    const int m0   = blockIdx.y * TM;
    const int n0   = blockIdx.x * 128;

    const __half* Arow = Ap + (size_t)m0 * D;
    const __half* Brow = Bp + (size_t)n0 * D;

    float acc[MF][8][4];
    #pragma unroll
    for (int i = 0; i < MF; i++)
        #pragma unroll
        for (int j = 0; j < 8; j++)
            #pragma unroll
            for (int r = 0; r < 4; r++) acc[i][j][r] = 0.f;

    const int arow  = lane & 15;
    const int akoff = (lane >> 4) * 16;
    const int bn    = (lane & 7) + ((lane >> 4) << 3);
    const int bkoff = ((lane >> 3) & 1) * 16;

    load_stage<TM>(sb + 0 * STAGE, Arow, Brow, 0, t);
    load_stage<TM>(sb + 1 * STAGE, Arow, Brow, BKG, t);

    int bufc = 0;
    for (int c = 0; c < NITER; c++) {
        if (c + 1 < NITER) { CP_WAIT1(); } else { CP_WAIT0(); }
        __syncthreads();                       // stage c visible; buf (c+2)%3 free

        const uint32_t sbase = sb + bufc * STAGE;
        #pragma unroll
        for (int kk = 0; kk < 2; kk++) {
            const uint32_t kbyte = kk * 32;
            uint32_t ah[MF][4];
            #pragma unroll
            for (int mf = 0; mf < MF; mf++) {
                uint32_t ad = sbase + (wm + mf * 16 + arow) * (LDT * 2) + kbyte + akoff;
                ldsm_x4(ah[mf], ad);
            }
            #pragma unroll
            for (int nb = 0; nb < 4; nb++) {
                uint32_t bh4[4];
                uint32_t bd = sbase + A_TILE + (wn + nb * 16 + bn) * (LDT * 2) + kbyte + bkoff;
                ldsm_x4(bh4, bd);
                #pragma unroll
                for (int mf = 0; mf < MF; mf++)
                    #pragma unroll
                    for (int half = 0; half < 2; half++) {
                        int nf = nb * 2 + half;
                        mma16816h(acc[mf][nf], ah[mf], &bh4[half * 2]);
                    }
            }
        }
        // Issue next-next stage AFTER compute; its buffer was last read at
        // iter c-1 and all warps passed this iter's barrier -> no hazard.
        if (c + 2 < NITER) {
            int bufn = bufc + 2; if (bufn >= 3) bufn -= 3;
            load_stage<TM>(sb + bufn * STAGE, Arow, Brow, (c + 2) * BKG, t);
        }
        if (++bufc == 3) bufc = 0;
    }

    // Epilogue
    const int rbase = m0 + wm + (lane >> 2);
    const int cbase = n0 + wn + (lane & 3) * 2;
    #pragma unroll
    for (int mf = 0; mf < MF; mf++) {
        #pragma unroll
        for (int nf = 0; nf < 8; nf++) {
            int col = cbase + nf * 8;
            float2 bv = *(const float2*)(bias + col);
            int r0 = rbase + mf * 16;
            float v0 = acc[mf][nf][0] + bv.x, v1 = acc[mf][nf][1] + bv.y;
            float v2 = acc[mf][nf][2] + bv.x, v3 = acc[mf][nf][3] + bv.y;
            if (MODE == 0) {
                float2 o0 = {v0, v1}, o1 = {v2, v3};
                *(float2*)(C + (size_t)r0 * D + col)       = o0;
                *(float2*)(C + (size_t)(r0 + 8) * D + col) = o1;
            } else {
                *(uint32_t*)(F + (size_t)r0 * D + col) =
                    pack_f16(__float2half_rn(v0), __float2half_rn(v1));
                *(uint32_t*)(F + (size_t)(r0 + 8) * D + col) =
                    pack_f16(__float2half_rn(v2), __float2half_rn(v3));
            }
        }
    }
}

// Q/K/V projections: 1-pass fp16, 128x128 tiles
__global__ __launch_bounds__(128, 2) void qkv_tc_gemm(const float* __restrict__ bq,
                                                      const float* __restrict__ bk,
                                                      const float* __restrict__ bv) {
    const int z = blockIdx.z;
    const __half* W = g_wT16 + (size_t)z * D * D;
    const float* bias = (z == 0) ? bq : (z == 1) ? bk : bv;
    __half* Out = (z == 0) ? g_q16 : (z == 1) ? g_k16 : g_v16;
    tc_gemm_body<128, 2>(g_x16, W, bias, nullptr, Out);
}

// Output projection: 1-pass, fp32 out, 64x128 tiles (2048 CTAs -> full waves)
__global__ __launch_bounds__(128, 2) void out_tc_gemm(const float* __restrict__ bo,
                                                      float* __restrict__ out) {
    tc_gemm_body<64, 0>(g_c16, g_wT16 + (size_t)3 * D * D, bo, out, nullptr);
}

// ---------------------------------------------------------------------------
// Tensor-core flash attention (fp16, causal). Br=Bc=64, 128 threads.
// Software-pipelined: PV(jb-1) fused/interleaved with softmax(jb); exp2 on
// the MUFU pipe. First PV skipped (jb==0 branch). 3 K/V smem buffers.
// ---------------------------------------------------------------------------
constexpr int AT_LDB   = 272;                    // bytes per tile row (128 f16 + pad)
constexpr int AT_TILE  = 64 * AT_LDB;            // 17408 B
constexpr int ATTN_SMEM = 6 * AT_TILE;           // 3 KV buffers (Q reuses tile 0)
constexpr float SCALE_LOG2E = 0.12751650f;       // (1/sqrt(128)) * log2(e)

__global__ __launch_bounds__(128, 2) void attn_tc_kernel() {
    extern __shared__ char sm8[];
    const uint32_t sb = smem_u32(sm8);

    const int t    = threadIdx.x;
    const int lane = t & 31;
    const int w    = t >> 5;
    const int iq   = (gridDim.x - 1) - blockIdx.x;      // big blocks first
    const int bh   = blockIdx.y;
    const int b    = bh >> 4;
    const int h    = bh & 15;
    const int q0   = iq * 64;
    const int wq   = w * 16;

    // ldmatrix lane offsets
    const int arow  = lane & 15;
    const int akoff = (lane >> 4) * 16;
    const int bn    = (lane & 7) + ((lane >> 4) << 3);
    const int bkoff = ((lane >> 3) & 1) * 16;
    const int vrow  = lane & 15;
    const int vcol  = (lane >> 4) << 3;

    // ---- Load Q into tile 0, hoist to registers ----
    {
        #pragma unroll
        for (int i = 0; i < 8; i++) {
            int idx  = t + 128 * i;
            int row  = idx >> 4;
            int chnk = idx & 15;
            size_t g = (size_t)(b * S + q0 + row) * D + h * DH + chnk * 8;
            cp_async16(sb + row * AT_LDB + chnk * 16, g_q16 + g);
        }
        CP_COMMIT();
        CP_WAIT0();
        __syncthreads();
    }
    uint32_t qhr[8][4];
    #pragma unroll
    for (int kt = 0; kt < 8; kt++) {
        ldsm_x4(qhr[kt], sb + (wq + arow) * AT_LDB + kt * 32 + akoff);
    }
    __syncthreads();   // all warps' Q reads done before KV(0) overwrites tile 0

    // ---- Issue KV(0) -> buf0, KV(1) -> buf1 ----
    #pragma unroll
    for (int i = 0; i < 8; i++) {
        int idx  = t + 128 * i;
        int row  = idx >> 4;
        int chnk = idx & 15;
        size_t g = (size_t)(b * S + row) * D + h * DH + chnk * 8;
        uint32_t so = row * AT_LDB + chnk * 16;
        cp_async16(sb + so, g_k16 + g);
        cp_async16(sb + AT_TILE + so, g_v16 + g);
    }
    CP_COMMIT();
    if (iq >= 1) {
        #pragma unroll
        for (int i = 0; i < 8; i++) {
            int idx  = t + 128 * i;
            int row  = idx >> 4;
            int chnk = idx & 15;
            size_t g = (size_t)(b * S + 64 + row) * D + h * DH + chnk * 8;
            uint32_t so = row * AT_LDB + chnk * 16;
            cp_async16(sb + 2 * AT_TILE + so, g_k16 + g);
            cp_async16(sb + 3 * AT_TILE + so, g_v16 + g);
        }
        CP_COMMIT();
    }

    float o[16][4];
    #pragma unroll
    for (int i = 0; i < 16; i++)
        #pragma unroll
        for (int r = 0; r < 4; r++) o[i][r] = 0.f;
    float m0 = -1e30f, m1 = -1e30f, l0 = 0.f, l1 = 0.f;
    uint32_t pahp[4][4];
    #pragma unroll
    for (int g = 0; g < 4; g++)
        #pragma unroll
        for (int q = 0; q < 4; q++) pahp[g][q] = 0u;
    float scp0 = 1.f, scp1 = 1.f;

    const int r0g = q0 + wq + (lane >> 2);
    const int r1g = r0g + 8;

    int cur = 0;
    for (int jb = 0; jb <= iq; jb++) {
        const int prv = (cur + 2 >= 3) ? cur - 1 : cur + 2;   // (jb-1)%3 == (jb+2)%3
        if (jb < iq) { CP_WAIT1(); } else { CP_WAIT0(); }
        __syncthreads();                     // KV(jb) visible to all warps

        const uint32_t Kb = sb + (2 * cur) * AT_TILE;
        const uint32_t Vp = sb + (2 * prv + 1) * AT_TILE;     // V(jb-1)
        const int k0 = jb * 64;

        // ---- S = Q K^T (single pass, fp16) ----
        float c[8][4];
        #pragma unroll
        for (int j = 0; j < 8; j++)
            #pragma unroll
            for (int r = 0; r < 4; r++) c[j][r] = 0.f;

        #pragma unroll
        for (int kt = 0; kt < 8; kt++) {
            #pragma unroll
            for (int nb = 0; nb < 4; nb++) {
                uint32_t kh4[4];
                ldsm_x4(kh4, Kb + (nb * 16 + bn) * AT_LDB + kt * 32 + bkoff);
                #pragma unroll
                for (int half = 0; half < 2; half++) {
                    int nf = nb * 2 + half;
                    mma16816h(c[nf], qhr[kt], &kh4[half * 2]);
                }
            }
        }

        // ---- scale (+ causal mask only on the diagonal block) ----
        if (jb == iq) {
            #pragma unroll
            for (int j = 0; j < 8; j++) {
                int cc = k0 + j * 8 + (lane & 3) * 2;
                #pragma unroll
                for (int r = 0; r < 4; r++) {
                    float v = c[j][r] * SCALE_LOG2E;
                    int col = cc + (r & 1);
                    int row = (r < 2) ? r0g : r1g;
                    if (col > row) v = -1e30f;
                    c[j][r] = v;
                }
            }
        } else {
            #pragma unroll
            for (int j = 0; j < 8; j++)
                #pragma unroll
                for (int r = 0; r < 4; r++)
                    c[j][r] *= SCALE_LOG2E;
        }

        // ---- row max + running max ----
        float mx0 = -1e30f, mx1 = -1e30f;
        #pragma unroll
        for (int j = 0; j < 8; j++) {
            mx0 = fmaxf(mx0, fmaxf(c[j][0], c[j][1]));
            mx1 = fmaxf(mx1, fmaxf(c[j][2], c[j][3]));
        }
        mx0 = fmaxf(mx0, __shfl_xor_sync(0xffffffffu, mx0, 1));
        mx0 = fmaxf(mx0, __shfl_xor_sync(0xffffffffu, mx0, 2));
        mx1 = fmaxf(mx1, __shfl_xor_sync(0xffffffffu, mx1, 1));
        mx1 = fmaxf(mx1, __shfl_xor_sync(0xffffffffu, mx1, 2));
        float mn0 = fmaxf(m0, mx0), mn1 = fmaxf(m1, mx1);
        float sc0 = exp2_mufu(m0 - mn0), sc1 = exp2_mufu(m1 - mn1);
        m0 = mn0; m1 = mn1;

        // ---- rescale O by PREVIOUS sc (before adding PV(jb-1)) ----
        #pragma unroll
        for (int nf = 0; nf < 16; nf++) {
            o[nf][0] *= scp0; o[nf][1] *= scp0;
            o[nf][2] *= scp1; o[nf][3] *= scp1;
        }

        // ---- FUSED: PV(jb-1) [tensor, skipped on jb==0] + exp2 [MUFU] ----
        float ls0 = 0.f, ls1 = 0.f;
        uint32_t pah[4][4];
        #pragma unroll
        for (int g = 0; g < 4; g++) {
            if (jb > 0) {
                #pragma unroll
                for (int vb = 0; vb < 8; vb++) {
                    uint32_t vh4[4];
                    ldsm_x4_t(vh4, Vp + (g * 16 + vrow) * AT_LDB + (vb * 16 + vcol) * 2);
                    #pragma unroll
                    for (int half = 0; half < 2; half++) {
                        int nf = vb * 2 + half;
                        mma16816h(o[nf], pahp[g], &vh4[half * 2]);
                    }
                }
            }
            #pragma unroll
            for (int jj = 0; jj < 2; jj++) {
                int j = 2 * g + jj;
                c[j][0] = exp2_mufu(c[j][0] - mn0);
                c[j][1] = exp2_mufu(c[j][1] - mn0);
                c[j][2] = exp2_mufu(c[j][2] - mn1);
                c[j][3] = exp2_mufu(c[j][3] - mn1);
                ls0 += c[j][0] + c[j][1];
                ls1 += c[j][2] + c[j][3];
            }
            #pragma unroll
            for (int q = 0; q < 4; q++) {
                int j = 2 * g + (q >> 1);
                int e = (q & 1) * 2;
                pah[g][q] = pack_f16(__float2half_rn(c[j][e]),
                                     __float2half_rn(c[j][e + 1]));
            }
        }

        // ---- finish softmax stats ----
        ls0 += __shfl_xor_sync(0xffffffffu, ls0, 1);
        ls0 += __shfl_xor_sync(0xffffffffu, ls0, 2);
        ls1 += __shfl_xor_sync(0xffffffffu, ls1, 1);
        ls1 += __shfl_xor_sync(0xffffffffu, ls1, 2);
        l0 = l0 * sc0 + ls0;
        l1 = l1 * sc1 + ls1;

        // carry P and sc to next iteration
        #pragma unroll
        for (int g = 0; g < 4; g++)
            #pragma unroll
            for (int q = 0; q < 4; q++) pahp[g][q] = pah[g][q];
        scp0 = sc0; scp1 = sc1;

        __syncthreads();                     // everyone done with V(jb-1) buffer
        if (jb + 2 <= iq) {                  // load KV(jb+2) into buffer prv
            const int kn = (jb + 2) * 64;
            const uint32_t buf = sb + (2 * prv) * AT_TILE;
            #pragma unroll
            for (int i = 0; i < 8; i++) {
                int idx  = t + 128 * i;
                int row  = idx >> 4;
                int chnk = idx & 15;
                size_t g = (size_t)(b * S + kn + row) * D + h * DH + chnk * 8;
                uint32_t so = row * AT_LDB + chnk * 16;
                cp_async16(buf + so, g_k16 + g);
                cp_async16(buf + AT_TILE + so, g_v16 + g);
            }
            CP_COMMIT();
        }
        cur = (cur + 1 >= 3) ? 0 : cur + 1;
    }

    // ---- epilogue: final rescale + PV(iq), then normalize and store ----
    {
        const int curv = iq % 3;
        const uint32_t Vl = sb + (2 * curv + 1) * AT_TILE;
        #pragma unroll
        for (int nf = 0; nf < 16; nf++) {
            o[nf][0] *= scp0; o[nf][1] *= scp0;
            o[nf][2] *= scp1; o[nf][3] *= scp1;
        }
        #pragma unroll
        for (int g = 0; g < 4; g++) {
            #pragma unroll
            for (int vb = 0; vb < 8; vb++) {
                uint32_t vh4[4];
                ldsm_x4_t(vh4, Vl + (g * 16 + vrow) * AT_LDB + (vb * 16 + vcol) * 2);
                #pragma unroll
                for (int half = 0; half < 2; half++) {
                    int nf = vb * 2 + half;
                    mma16816h(o[nf], pahp[g], &vh4[half * 2]);
                }
            }
        }
    }

    const float inv0 = 1.f / l0, inv1 = 1.f / l1;
    const int colb = h * DH + (lane & 3) * 2;
    #pragma unroll
    for (int nf = 0; nf < 16; nf++) {
        int col = colb + nf * 8;
        size_t g0 = (size_t)(b * S + r0g) * D + col;
        size_t g1 = (size_t)(b * S + r1g) * D + col;
        *(uint32_t*)(g_c16 + g0) =
            pack_f16(__float2half_rn(o[nf][0] * inv0), __float2half_rn(o[nf][1] * inv0));
        *(uint32_t*)(g_c16 + g1) =
            pack_f16(__float2half_rn(o[nf][2] * inv1), __float2half_rn(o[nf][3] * inv1));
    }
}

// ---------------------------------------------------------------------------
extern "C" void kernel_launch(void* const* d_in, const int* in_sizes, int n_in,
                              void* d_out, int out_size)
{
    const float* X  = (const float*)d_in[0];
    const float* Wq = (const float*)d_in[1];
    const float* bq = (const float*)d_in[2];
    const float* Wk = (const float*)d_in[3];
    const float* bk = (const float*)d_in[4];
    const float* Wv = (const float*)d_in[5];
    const float* bv = (const float*)d_in[6];
    const float* Wo = (const float*)d_in[7];
    const float* bo = (const float*)d_in[8];
    float* out = (float*)d_out;

    cudaFuncSetAttribute(attn_tc_kernel, cudaFuncAttributeMaxDynamicSharedMemorySize, ATTN_SMEM);
    cudaFuncSetAttribute(qkv_tc_gemm, cudaFuncAttributeMaxDynamicSharedMemorySize, GEMM_SMEM_128);
    cudaFuncSetAttribute(out_tc_gemm, cudaFuncAttributeMaxDynamicSharedMemorySize, GEMM_SMEM_64);

    conv_x_kernel<<<(M * D / 4) / 256, 256>>>((const float4*)X);
    wsplit_kernel<<<dim3(D / 32, D / 32, 4), 256>>>(Wq, Wk, Wv, Wo);
    qkv_tc_gemm<<<dim3(D / 128, M / 128, 3), 128, GEMM_SMEM_128>>>(bq, bk, bv);
    attn_tc_kernel<<<dim3(S / 64, B * H), 128, ATTN_SMEM>>>();
    out_tc_gemm<<<dim3(D / 128, M / 64), 128, GEMM_SMEM_64>>>(bo, out);
}

// round 16
// speedup vs baseline: 1.0578x; 1.0578x over previous
#include <cuda_runtime.h>
#include <cuda_bf16.h>
#include <cuda_fp16.h>
#include <math.h>
#include <cstdint>

// Problem constants
constexpr int B  = 4;
constexpr int S  = 2048;
constexpr int D  = 2048;
constexpr int H  = 16;
constexpr int DH = 128;
constexpr int M  = B * S;          // 8192 rows

// ---------------------------------------------------------------------------
// Scratch (allocation-free rule: device globals). fp16 everywhere.
// ---------------------------------------------------------------------------
__device__ __half g_x16[(size_t)M * D];
__device__ __half g_q16[(size_t)M * D];
__device__ __half g_k16[(size_t)M * D];
__device__ __half g_v16[(size_t)M * D];
__device__ __half g_c16[(size_t)M * D];
__device__ __half g_wT16[(size_t)4 * D * D];   // [w][N][K] single fp16

// ---------------------------------------------------------------------------
// PTX helpers (sm_103 baseline: mma.sync + ldmatrix + cp.async only)
// ---------------------------------------------------------------------------
__device__ __forceinline__ uint32_t smem_u32(const void* p) {
    uint32_t a;
    asm("{ .reg .u64 t; cvta.to.shared.u64 t, %1; cvt.u32.u64 %0, t; }" : "=r"(a) : "l"(p));
    return a;
}

__device__ __forceinline__ void cp_async16(uint32_t dst, const void* src) {
    asm volatile("cp.async.cg.shared.global [%0], [%1], 16;" :: "r"(dst), "l"(src));
}
#define CP_COMMIT() asm volatile("cp.async.commit_group;" ::: "memory")
#define CP_WAIT0()  asm volatile("cp.async.wait_group 0;" ::: "memory")
#define CP_WAIT1()  asm volatile("cp.async.wait_group 1;" ::: "memory")

__device__ __forceinline__ void ldsm_x4(uint32_t* r, uint32_t addr) {
    asm volatile("ldmatrix.sync.aligned.m8n8.x4.shared.b16 {%0,%1,%2,%3}, [%4];"
        : "=r"(r[0]), "=r"(r[1]), "=r"(r[2]), "=r"(r[3]) : "r"(addr));
}
__device__ __forceinline__ void ldsm_x4_t(uint32_t* r, uint32_t addr) {
    asm volatile("ldmatrix.sync.aligned.m8n8.x4.trans.shared.b16 {%0,%1,%2,%3}, [%4];"
        : "=r"(r[0]), "=r"(r[1]), "=r"(r[2]), "=r"(r[3]) : "r"(addr));
}

__device__ __forceinline__ void mma16816h(float* c, const uint32_t* a, const uint32_t* b) {
    asm volatile("mma.sync.aligned.m16n8k16.row.col.f32.f16.f16.f32 "
        "{%0,%1,%2,%3}, {%4,%5,%6,%7}, {%8,%9}, {%0,%1,%2,%3};"
        : "+f"(c[0]), "+f"(c[1]), "+f"(c[2]), "+f"(c[3])
        : "r"(a[0]), "r"(a[1]), "r"(a[2]), "r"(a[3]), "r"(b[0]), "r"(b[1]));
}

__device__ __forceinline__ uint32_t pack_f16(__half lo, __half hi) {
    __half2 h2 = __halves2half2(lo, hi);
    return *(uint32_t*)&h2;
}

// 2^z on the MUFU pipe (1 instruction; flushes large-negative to 0).
__device__ __forceinline__ float exp2_mufu(float z) {
    float r;
    asm("ex2.approx.f32 %0, %1;" : "=f"(r) : "f"(z));
    return r;
}

// ---------------------------------------------------------------------------
// Conversion kernels
// ---------------------------------------------------------------------------
__global__ __launch_bounds__(256) void conv_x_kernel(const float4* __restrict__ in) {
    size_t i = (size_t)blockIdx.x * blockDim.x + threadIdx.x;
    float4 v = in[i];
    __half h[4] = {__float2half_rn(v.x), __float2half_rn(v.y),
                   __float2half_rn(v.z), __float2half_rn(v.w)};
    *(uint2*)(g_x16 + i * 4) = *(const uint2*)h;
}

// Weights: W [K][N] fp32 -> transposed single fp16 [N][K]
__global__ __launch_bounds__(256) void wsplit_kernel(const float* __restrict__ Wq,
                                                     const float* __restrict__ Wk,
                                                     const float* __restrict__ Wv,
                                                     const float* __restrict__ Wo) {
    __shared__ float tile[32][33];
    int z = blockIdx.z;
    const float* W = (z == 0) ? Wq : (z == 1) ? Wk : (z == 2) ? Wv : Wo;
    __half* oh = g_wT16 + (size_t)z * D * D;
    int n0 = blockIdx.x * 32, k0 = blockIdx.y * 32;
    int tx = threadIdx.x & 31, ty = threadIdx.x >> 5;
    #pragma unroll
    for (int i = 0; i < 4; i++) {
        int k = ty + i * 8;
        tile[k][tx] = W[(size_t)(k0 + k) * D + n0 + tx];
    }
    __syncthreads();
    #pragma unroll
    for (int i = 0; i < 4; i++) {
        int n = ty + i * 8;
        oh[(size_t)(n0 + n) * D + k0 + tx] = __float2half_rn(tile[tx][n]);
    }
}

// ---------------------------------------------------------------------------
// mma.sync fp16 1-pass GEMM: C[128x128] = A @ B^T + bias
// 4 warps (2x2), warp tile 64x64, BK=32, 3-stage cp.async, ONE sync/iter.
// MODE: 0 = fp32 out, 2 = fp16 out
// ---------------------------------------------------------------------------
constexpr int BKG      = 32;
constexpr int LDT      = 40;                 // f16 stride per tile row (80 B)
constexpr int TILE_BY  = 128 * LDT * 2;      // 10240 B per tile
constexpr int NITER    = D / BKG;            // 64
constexpr int GEMM_SMEM2 = 3 * 2 * TILE_BY;  // 61440 B

__device__ __forceinline__ void load_stage(uint32_t sbase,
                                           const __half* A,
                                           const __half* Bm,
                                           int k0, int t) {
    const __half* bases[2] = {A, Bm};
    #pragma unroll
    for (int i = 0; i < 8; i++) {
        const int tile = i >> 2;              // 4 slots per tile per thread
        int idx  = t + 128 * (i & 3);         // 0..511
        int row  = idx >> 2;                  // 0..127
        int chnk = idx & 3;                   // 16B chunk
        const __half* src = bases[tile] + (size_t)row * D + k0 + chnk * 8;
        uint32_t dst = sbase + tile * TILE_BY + row * (LDT * 2) + chnk * 16;
        cp_async16(dst, src);
    }
    CP_COMMIT();
}

template <int MODE>
__device__ __forceinline__ void tc_gemm_body(const __half* __restrict__ Ap,
                                             const __half* __restrict__ Bp,
                                             const float* __restrict__ bias,
                                             float* __restrict__ C,
                                             __half* __restrict__ F) {
    constexpr int STAGE = 2 * TILE_BY;
    extern __shared__ char smem[];
    const uint32_t sb = smem_u32(smem);
    const int t    = threadIdx.x;
    const int lane = t & 31;
    const int w    = t >> 5;
    const int wm   = (w & 1) * 64;
    const int wn   = (w >> 1) * 64;
    const int m0   = blockIdx.y * 128;
    const int n0   = blockIdx.x * 128;

    const __half* Arow = Ap + (size_t)m0 * D;
    const __half* Brow = Bp + (size_t)n0 * D;

    float acc[4][8][4];
    #pragma unroll
    for (int i = 0; i < 4; i++)
        #pragma unroll
        for (int j = 0; j < 8; j++)
            #pragma unroll
            for (int r = 0; r < 4; r++) acc[i][j][r] = 0.f;

    const int arow  = lane & 15;
    const int akoff = (lane >> 4) * 16;
    const int bn    = (lane & 7) + ((lane >> 4) << 3);
    const int bkoff = ((lane >> 3) & 1) * 16;

    load_stage(sb + 0 * STAGE, Arow, Brow, 0, t);
    load_stage(sb + 1 * STAGE, Arow, Brow, BKG, t);

    int bufc = 0;
    for (int c = 0; c < NITER; c++) {
        if (c + 1 < NITER) { CP_WAIT1(); } else { CP_WAIT0(); }
        __syncthreads();                       // stage c visible; buf (c+2)%3 free

        const uint32_t sbase = sb + bufc * STAGE;
        #pragma unroll
        for (int kk = 0; kk < 2; kk++) {
            const uint32_t kbyte = kk * 32;
            uint32_t ah[4][4];
            #pragma unroll
            for (int mf = 0; mf < 4; mf++) {
                uint32_t ad = sbase + (wm + mf * 16 + arow) * (LDT * 2) + kbyte + akoff;
                ldsm_x4(ah[mf], ad);
            }
            #pragma unroll
            for (int nb = 0; nb < 4; nb++) {
                uint32_t bh4[4];
                uint32_t bd = sbase + TILE_BY + (wn + nb * 16 + bn) * (LDT * 2) + kbyte + bkoff;
                ldsm_x4(bh4, bd);
                #pragma unroll
                for (int mf = 0; mf < 4; mf++)
                    #pragma unroll
                    for (int half = 0; half < 2; half++) {
                        int nf = nb * 2 + half;
                        mma16816h(acc[mf][nf], ah[mf], &bh4[half * 2]);
                    }
            }
        }
        // Issue next-next stage AFTER compute; its buffer was last read at
        // iter c-1 and all warps passed this iter's barrier -> no hazard.
        if (c + 2 < NITER) {
            int bufn = bufc + 2; if (bufn >= 3) bufn -= 3;
            load_stage(sb + bufn * STAGE, Arow, Brow, (c + 2) * BKG, t);
        }
        if (++bufc == 3) bufc = 0;
    }

    // Epilogue
    const int rbase = m0 + wm + (lane >> 2);
    const int cbase = n0 + wn + (lane & 3) * 2;
    #pragma unroll
    for (int mf = 0; mf < 4; mf++) {
        #pragma unroll
        for (int nf = 0; nf < 8; nf++) {
            int col = cbase + nf * 8;
            float2 bv = *(const float2*)(bias + col);
            int r0 = rbase + mf * 16;
            float v0 = acc[mf][nf][0] + bv.x, v1 = acc[mf][nf][1] + bv.y;
            float v2 = acc[mf][nf][2] + bv.x, v3 = acc[mf][nf][3] + bv.y;
            if (MODE == 0) {
                float2 o0 = {v0, v1}, o1 = {v2, v3};
                *(float2*)(C + (size_t)r0 * D + col)       = o0;
                *(float2*)(C + (size_t)(r0 + 8) * D + col) = o1;
            } else {
                *(uint32_t*)(F + (size_t)r0 * D + col) =
                    pack_f16(__float2half_rn(v0), __float2half_rn(v1));
                *(uint32_t*)(F + (size_t)(r0 + 8) * D + col) =
                    pack_f16(__float2half_rn(v2), __float2half_rn(v3));
            }
        }
    }
}

// Q/K/V projections: 1-pass fp16
__global__ __launch_bounds__(128, 2) void qkv_tc_gemm(const float* __restrict__ bq,
                                                      const float* __restrict__ bk,
                                                      const float* __restrict__ bv) {
    const int z = blockIdx.z;
    const __half* W = g_wT16 + (size_t)z * D * D;
    const float* bias = (z == 0) ? bq : (z == 1) ? bk : bv;
    __half* Out = (z == 0) ? g_q16 : (z == 1) ? g_k16 : g_v16;
    tc_gemm_body<2>(g_x16, W, bias, nullptr, Out);
}

// Output projection: 1-pass, fp32 out
__global__ __launch_bounds__(128, 2) void out_tc_gemm(const float* __restrict__ bo,
                                                      float* __restrict__ out) {
    tc_gemm_body<0>(g_c16, g_wT16 + (size_t)3 * D * D, bo, out, nullptr);
}

// ---------------------------------------------------------------------------
// Tensor-core flash attention (fp16, causal). Br=Bc=64, 128 threads.
// Software-pipelined: PV(jb-1) fused/interleaved with softmax(jb); exp2 on
// the MUFU pipe (idle otherwise). Branchless first iteration (zeroed V tile).
// 3 K/V smem buffers.
// ---------------------------------------------------------------------------
constexpr int AT_LDB   = 272;                    // bytes per tile row (128 f16 + pad)
constexpr int AT_TILE  = 64 * AT_LDB;            // 17408 B
constexpr int ATTN_SMEM = 6 * AT_TILE;           // 3 KV buffers (Q reuses tile 0)
constexpr float SCALE_LOG2E = 0.12751650f;       // (1/sqrt(128)) * log2(e)

__global__ __launch_bounds__(128, 2) void attn_tc_kernel() {
    extern __shared__ char sm8[];
    const uint32_t sb = smem_u32(sm8);

    const int t    = threadIdx.x;
    const int lane = t & 31;
    const int w    = t >> 5;
    const int iq   = (gridDim.x - 1) - blockIdx.x;      // big blocks first
    const int bh   = blockIdx.y;
    const int b    = bh >> 4;
    const int h    = bh & 15;
    const int q0   = iq * 64;
    const int wq   = w * 16;

    // ldmatrix lane offsets
    const int arow  = lane & 15;
    const int akoff = (lane >> 4) * 16;
    const int bn    = (lane & 7) + ((lane >> 4) << 3);
    const int bkoff = ((lane >> 3) & 1) * 16;
    const int vrow  = lane & 15;
    const int vcol  = (lane >> 4) << 3;

    // ---- Load Q into tile 0, hoist to registers ----
    {
        #pragma unroll
        for (int i = 0; i < 8; i++) {
            int idx  = t + 128 * i;
            int row  = idx >> 4;
            int chnk = idx & 15;
            size_t g = (size_t)(b * S + q0 + row) * D + h * DH + chnk * 8;
            cp_async16(sb + row * AT_LDB + chnk * 16, g_q16 + g);
        }
        CP_COMMIT();
        CP_WAIT0();
        __syncthreads();
    }
    uint32_t qhr[8][4];
    #pragma unroll
    for (int kt = 0; kt < 8; kt++) {
        ldsm_x4(qhr[kt], sb + (wq + arow) * AT_LDB + kt * 32 + akoff);
    }
    // Zero V tile of buffer 2 (tile 5): first-iteration dummy PV reads it.
    for (uint32_t i = (uint32_t)t * 16; i < (uint32_t)AT_TILE; i += 128 * 16) {
        *(uint4*)(sm8 + 5 * AT_TILE + i) = make_uint4(0, 0, 0, 0);
    }
    __syncthreads();   // Q reads + zeroing done before KV(0) overwrites tile 0

    // ---- Issue KV(0) -> buf0, KV(1) -> buf1 ----
    #pragma unroll
    for (int i = 0; i < 8; i++) {
        int idx  = t + 128 * i;
        int row  = idx >> 4;
        int chnk = idx & 15;
        size_t g = (size_t)(b * S + row) * D + h * DH + chnk * 8;
        uint32_t so = row * AT_LDB + chnk * 16;
        cp_async16(sb + so, g_k16 + g);
        cp_async16(sb + AT_TILE + so, g_v16 + g);
    }
    CP_COMMIT();
    if (iq >= 1) {
        #pragma unroll
        for (int i = 0; i < 8; i++) {
            int idx  = t + 128 * i;
            int row  = idx >> 4;
            int chnk = idx & 15;
            size_t g = (size_t)(b * S + 64 + row) * D + h * DH + chnk * 8;
            uint32_t so = row * AT_LDB + chnk * 16;
            cp_async16(sb + 2 * AT_TILE + so, g_k16 + g);
            cp_async16(sb + 3 * AT_TILE + so, g_v16 + g);
        }
        CP_COMMIT();
    }

    float o[16][4];
    #pragma unroll
    for (int i = 0; i < 16; i++)
        #pragma unroll
        for (int r = 0; r < 4; r++) o[i][r] = 0.f;
    float m0 = -1e30f, m1 = -1e30f, l0 = 0.f, l1 = 0.f;
    uint32_t pahp[4][4];
    #pragma unroll
    for (int g = 0; g < 4; g++)
        #pragma unroll
        for (int q = 0; q < 4; q++) pahp[g][q] = 0u;   // P(-1) = 0
    float scp0 = 1.f, scp1 = 1.f;

    const int r0g = q0 + wq + (lane >> 2);
    const int r1g = r0g + 8;

    int cur = 0;
    for (int jb = 0; jb <= iq; jb++) {
        const int prv = (cur + 2 >= 3) ? cur - 1 : cur + 2;   // (jb-1)%3 == (jb+2)%3
        if (jb < iq) { CP_WAIT1(); } else { CP_WAIT0(); }
        __syncthreads();                     // KV(jb) visible to all warps

        const uint32_t Kb = sb + (2 * cur) * AT_TILE;
        const uint32_t Vp = sb + (2 * prv + 1) * AT_TILE;     // V(jb-1)
        const int k0 = jb * 64;

        // ---- S = Q K^T (single pass, fp16) ----
        float c[8][4];
        #pragma unroll
        for (int j = 0; j < 8; j++)
            #pragma unroll
            for (int r = 0; r < 4; r++) c[j][r] = 0.f;

        #pragma unroll
        for (int kt = 0; kt < 8; kt++) {
            #pragma unroll
            for (int nb = 0; nb < 4; nb++) {
                uint32_t kh4[4];
                ldsm_x4(kh4, Kb + (nb * 16 + bn) * AT_LDB + kt * 32 + bkoff);
                #pragma unroll
                for (int half = 0; half < 2; half++) {
                    int nf = nb * 2 + half;
                    mma16816h(c[nf], qhr[kt], &kh4[half * 2]);
                }
            }
        }

        // ---- scale (+ causal mask only on the diagonal block) ----
        if (jb == iq) {
            #pragma unroll
            for (int j = 0; j < 8; j++) {
                int cc = k0 + j * 8 + (lane & 3) * 2;
                #pragma unroll
                for (int r = 0; r < 4; r++) {
                    float v = c[j][r] * SCALE_LOG2E;
                    int col = cc + (r & 1);
                    int row = (r < 2) ? r0g : r1g;
                    if (col > row) v = -1e30f;
                    c[j][r] = v;
                }
            }
        } else {
            #pragma unroll
            for (int j = 0; j < 8; j++)
                #pragma unroll
                for (int r = 0; r < 4; r++)
                    c[j][r] *= SCALE_LOG2E;
        }

        // ---- row max + running max ----
        float mx0 = -1e30f, mx1 = -1e30f;
        #pragma unroll
        for (int j = 0; j < 8; j++) {
            mx0 = fmaxf(mx0, fmaxf(c[j][0], c[j][1]));
            mx1 = fmaxf(mx1, fmaxf(c[j][2], c[j][3]));
        }
        mx0 = fmaxf(mx0, __shfl_xor_sync(0xffffffffu, mx0, 1));
        mx0 = fmaxf(mx0, __shfl_xor_sync(0xffffffffu, mx0, 2));
        mx1 = fmaxf(mx1, __shfl_xor_sync(0xffffffffu, mx1, 1));
        mx1 = fmaxf(mx1, __shfl_xor_sync(0xffffffffu, mx1, 2));
        float mn0 = fmaxf(m0, mx0), mn1 = fmaxf(m1, mx1);
        float sc0 = exp2_mufu(m0 - mn0), sc1 = exp2_mufu(m1 - mn1);
        m0 = mn0; m1 = mn1;

        // ---- rescale O by PREVIOUS sc (skip when both are exactly 1) ----
        if (scp0 != 1.f || scp1 != 1.f) {
            #pragma unroll
            for (int nf = 0; nf < 16; nf++) {
                o[nf][0] *= scp0; o[nf][1] *= scp0;
                o[nf][2] *= scp1; o[nf][3] *= scp1;
            }
        }

        // ---- FUSED: PV(jb-1) [tensor] interleaved with exp2 [MUFU] ----
        float ls0 = 0.f, ls1 = 0.f;
        uint32_t pah[4][4];
        #pragma unroll
        for (int g = 0; g < 4; g++) {
            // tensor: PV(jb-1) row-group g
            #pragma unroll
            for (int vb = 0; vb < 8; vb++) {
                uint32_t vh4[4];
                ldsm_x4_t(vh4, Vp + (g * 16 + vrow) * AT_LDB + (vb * 16 + vcol) * 2);
                #pragma unroll
                for (int half = 0; half < 2; half++) {
                    int nf = vb * 2 + half;
                    mma16816h(o[nf], pahp[g], &vh4[half * 2]);
                }
            }
            // scalar/MUFU: exp2 + partial sums + pack for j = 2g, 2g+1
            #pragma unroll
            for (int jj = 0; jj < 2; jj++) {
                int j = 2 * g + jj;
                c[j][0] = exp2_mufu(c[j][0] - mn0);
                c[j][1] = exp2_mufu(c[j][1] - mn0);
                c[j][2] = exp2_mufu(c[j][2] - mn1);
                c[j][3] = exp2_mufu(c[j][3] - mn1);
                ls0 += c[j][0] + c[j][1];
                ls1 += c[j][2] + c[j][3];
            }
            #pragma unroll
            for (int q = 0; q < 4; q++) {
                int j = 2 * g + (q >> 1);
                int e = (q & 1) * 2;
                pah[g][q] = pack_f16(__float2half_rn(c[j][e]),
                                     __float2half_rn(c[j][e + 1]));
            }
        }

        // ---- finish softmax stats ----
        ls0 += __shfl_xor_sync(0xffffffffu, ls0, 1);
        ls0 += __shfl_xor_sync(0xffffffffu, ls0, 2);
        ls1 += __shfl_xor_sync(0xffffffffu, ls1, 1);
        ls1 += __shfl_xor_sync(0xffffffffu, ls1, 2);
        l0 = l0 * sc0 + ls0;
        l1 = l1 * sc1 + ls1;

        // carry P and sc to next iteration
        #pragma unroll
        for (int g = 0; g < 4; g++)
            #pragma unroll
            for (int q = 0; q < 4; q++) pahp[g][q] = pah[g][q];
        scp0 = sc0; scp1 = sc1;

        __syncthreads();                     // everyone done with V(jb-1) buffer
        if (jb + 2 <= iq) {                  // load KV(jb+2) into buffer prv
            const int kn = (jb + 2) * 64;
            const uint32_t buf = sb + (2 * prv) * AT_TILE;
            #pragma unroll
            for (int i = 0; i < 8; i++) {
                int idx  = t + 128 * i;
                int row  = idx >> 4;
                int chnk = idx & 15;
                size_t g = (size_t)(b * S + kn + row) * D + h * DH + chnk * 8;
                uint32_t so = row * AT_LDB + chnk * 16;
                cp_async16(buf + so, g_k16 + g);
                cp_async16(buf + AT_TILE + so, g_v16 + g);
            }
            CP_COMMIT();
        }
        cur = (cur + 1 >= 3) ? 0 : cur + 1;
    }

    // ---- epilogue: final rescale + PV(iq), then normalize and store ----
    {
        const int curv = iq % 3;
        const uint32_t Vl = sb + (2 * curv + 1) * AT_TILE;
        if (scp0 != 1.f || scp1 != 1.f) {
            #pragma unroll
            for (int nf = 0; nf < 16; nf++) {
                o[nf][0] *= scp0; o[nf][1] *= scp0;
                o[nf][2] *= scp1; o[nf][3] *= scp1;
            }
        }
        #pragma unroll
        for (int g = 0; g < 4; g++) {
            #pragma unroll
            for (int vb = 0; vb < 8; vb++) {
                uint32_t vh4[4];
                ldsm_x4_t(vh4, Vl + (g * 16 + vrow) * AT_LDB + (vb * 16 + vcol) * 2);
                #pragma unroll
                for (int half = 0; half < 2; half++) {
                    int nf = vb * 2 + half;
                    mma16816h(o[nf], pahp[g], &vh4[half * 2]);
                }
            }
        }
    }

    const float inv0 = 1.f / l0, inv1 = 1.f / l1;
    const int colb = h * DH + (lane & 3) * 2;
    #pragma unroll
    for (int nf = 0; nf < 16; nf++) {
        int col = colb + nf * 8;
        size_t g0 = (size_t)(b * S + r0g) * D + col;
        size_t g1 = (size_t)(b * S + r1g) * D + col;
        *(uint32_t*)(g_c16 + g0) =
            pack_f16(__float2half_rn(o[nf][0] * inv0), __float2half_rn(o[nf][1] * inv0));
        *(uint32_t*)(g_c16 + g1) =
            pack_f16(__float2half_rn(o[nf][2] * inv1), __float2half_rn(o[nf][3] * inv1));
    }
}

// ---------------------------------------------------------------------------
extern "C" void kernel_launch(void* const* d_in, const int* in_sizes, int n_in,
                              void* d_out, int out_size)
{
    const float* X  = (const float*)d_in[0];
    const float* Wq = (const float*)d_in[1];
    const float* bq = (const float*)d_in[2];
    const float* Wk = (const float*)d_in[3];
    const float* bk = (const float*)d_in[4];
    const float* Wv = (const float*)d_in[5];
    const float* bv = (const float*)d_in[6];
    const float* Wo = (const float*)d_in[7];
    const float* bo = (const float*)d_in[8];
    float* out = (float*)d_out;

    cudaFuncSetAttribute(attn_tc_kernel, cudaFuncAttributeMaxDynamicSharedMemorySize, ATTN_SMEM);
    cudaFuncSetAttribute(qkv_tc_gemm, cudaFuncAttributeMaxDynamicSharedMemorySize, GEMM_SMEM2);
    cudaFuncSetAttribute(out_tc_gemm, cudaFuncAttributeMaxDynamicSharedMemorySize, GEMM_SMEM2);

    conv_x_kernel<<<(M * D / 4) / 256, 256>>>((const float4*)X);
    wsplit_kernel<<<dim3(D / 32, D / 32, 4), 256>>>(Wq, Wk, Wv, Wo);
    qkv_tc_gemm<<<dim3(D / 128, M / 128, 3), 128, GEMM_SMEM2>>>(bq, bk, bv);
    attn_tc_kernel<<<dim3(S / 64, B * H), 128, ATTN_SMEM>>>();
    out_tc_gemm<<<dim3(D / 128, M / 128), 128, GEMM_SMEM2>>>(bo, out);
}

// round 17
// speedup vs baseline: 1.0692x; 1.0108x over previous
#include <cuda_runtime.h>
#include <cuda_bf16.h>
#include <cuda_fp16.h>
#include <math.h>
#include <cstdint>

// Problem constants
constexpr int B  = 4;
constexpr int S  = 2048;
constexpr int D  = 2048;
constexpr int H  = 16;
constexpr int DH = 128;
constexpr int M  = B * S;          // 8192 rows

// ---------------------------------------------------------------------------
// Scratch (allocation-free rule: device globals). fp16 everywhere.
// g_q16 holds q pre-scaled by (1/sqrt(128))*log2(e).
// ---------------------------------------------------------------------------
__device__ __half g_x16[(size_t)M * D];
__device__ __half g_q16[(size_t)M * D];
__device__ __half g_k16[(size_t)M * D];
__device__ __half g_v16[(size_t)M * D];
__device__ __half g_c16[(size_t)M * D];
__device__ __half g_wT16[(size_t)4 * D * D];   // [w][N][K] single fp16

// ---------------------------------------------------------------------------
// PTX helpers (sm_103 baseline: mma.sync + ldmatrix + cp.async only)
// ---------------------------------------------------------------------------
__device__ __forceinline__ uint32_t smem_u32(const void* p) {
    uint32_t a;
    asm("{ .reg .u64 t; cvta.to.shared.u64 t, %1; cvt.u32.u64 %0, t; }" : "=r"(a) : "l"(p));
    return a;
}

__device__ __forceinline__ void cp_async16(uint32_t dst, const void* src) {
    asm volatile("cp.async.cg.shared.global [%0], [%1], 16;" :: "r"(dst), "l"(src));
}
#define CP_COMMIT() asm volatile("cp.async.commit_group;" ::: "memory")
#define CP_WAIT0()  asm volatile("cp.async.wait_group 0;" ::: "memory")
#define CP_WAIT1()  asm volatile("cp.async.wait_group 1;" ::: "memory")

__device__ __forceinline__ void ldsm_x4(uint32_t* r, uint32_t addr) {
    asm volatile("ldmatrix.sync.aligned.m8n8.x4.shared.b16 {%0,%1,%2,%3}, [%4];"
        : "=r"(r[0]), "=r"(r[1]), "=r"(r[2]), "=r"(r[3]) : "r"(addr));
}
__device__ __forceinline__ void ldsm_x4_t(uint32_t* r, uint32_t addr) {
    asm volatile("ldmatrix.sync.aligned.m8n8.x4.trans.shared.b16 {%0,%1,%2,%3}, [%4];"
        : "=r"(r[0]), "=r"(r[1]), "=r"(r[2]), "=r"(r[3]) : "r"(addr));
}

__device__ __forceinline__ void mma16816h(float* c, const uint32_t* a, const uint32_t* b) {
    asm volatile("mma.sync.aligned.m16n8k16.row.col.f32.f16.f16.f32 "
        "{%0,%1,%2,%3}, {%4,%5,%6,%7}, {%8,%9}, {%0,%1,%2,%3};"
        : "+f"(c[0]), "+f"(c[1]), "+f"(c[2]), "+f"(c[3])
        : "r"(a[0]), "r"(a[1]), "r"(a[2]), "r"(a[3]), "r"(b[0]), "r"(b[1]));
}

__device__ __forceinline__ uint32_t pack_f16(__half lo, __half hi) {
    __half2 h2 = __halves2half2(lo, hi);
    return *(uint32_t*)&h2;
}

// 2^z on the MUFU pipe (1 instruction; flushes large-negative to 0).
__device__ __forceinline__ float exp2_mufu(float z) {
    float r;
    asm("ex2.approx.f32 %0, %1;" : "=f"(r) : "f"(z));
    return r;
}

constexpr float SCALE_LOG2E = 0.12751650f;       // (1/sqrt(128)) * log2(e)

// ---------------------------------------------------------------------------
// Conversion kernels
// ---------------------------------------------------------------------------
__global__ __launch_bounds__(256) void conv_x_kernel(const float4* __restrict__ in) {
    size_t i = (size_t)blockIdx.x * blockDim.x + threadIdx.x;
    float4 v = in[i];
    __half h[4] = {__float2half_rn(v.x), __float2half_rn(v.y),
                   __float2half_rn(v.z), __float2half_rn(v.w)};
    *(uint2*)(g_x16 + i * 4) = *(const uint2*)h;
}

// Weights: W [K][N] fp32 -> transposed single fp16 [N][K]
__global__ __launch_bounds__(256) void wsplit_kernel(const float* __restrict__ Wq,
                                                     const float* __restrict__ Wk,
                                                     const float* __restrict__ Wv,
                                                     const float* __restrict__ Wo) {
    __shared__ float tile[32][33];
    int z = blockIdx.z;
    const float* W = (z == 0) ? Wq : (z == 1) ? Wk : (z == 2) ? Wv : Wo;
    __half* oh = g_wT16 + (size_t)z * D * D;
    int n0 = blockIdx.x * 32, k0 = blockIdx.y * 32;
    int tx = threadIdx.x & 31, ty = threadIdx.x >> 5;
    #pragma unroll
    for (int i = 0; i < 4; i++) {
        int k = ty + i * 8;
        tile[k][tx] = W[(size_t)(k0 + k) * D + n0 + tx];
    }
    __syncthreads();
    #pragma unroll
    for (int i = 0; i < 4; i++) {
        int n = ty + i * 8;
        oh[(size_t)(n0 + n) * D + k0 + tx] = __float2half_rn(tile[tx][n]);
    }
}

// ---------------------------------------------------------------------------
// mma.sync fp16 1-pass GEMM: C[128x128] = (A @ B^T + bias) * oscale
// 4 warps (2x2), warp tile 64x64, BK=32, 3-stage cp.async, ONE sync/iter.
// MODE: 0 = fp32 out, 2 = fp16 out
// ---------------------------------------------------------------------------
constexpr int BKG      = 32;
constexpr int LDT      = 40;                 // f16 stride per tile row (80 B)
constexpr int TILE_BY  = 128 * LDT * 2;      // 10240 B per tile
constexpr int NITER    = D / BKG;            // 64
constexpr int GEMM_SMEM2 = 3 * 2 * TILE_BY;  // 61440 B

__device__ __forceinline__ void load_stage(uint32_t sbase,
                                           const __half* A,
                                           const __half* Bm,
                                           int k0, int t) {
    const __half* bases[2] = {A, Bm};
    #pragma unroll
    for (int i = 0; i < 8; i++) {
        const int tile = i >> 2;              // 4 slots per tile per thread
        int idx  = t + 128 * (i & 3);         // 0..511
        int row  = idx >> 2;                  // 0..127
        int chnk = idx & 3;                   // 16B chunk
        const __half* src = bases[tile] + (size_t)row * D + k0 + chnk * 8;
        uint32_t dst = sbase + tile * TILE_BY + row * (LDT * 2) + chnk * 16;
        cp_async16(dst, src);
    }
    CP_COMMIT();
}

template <int MODE>
__device__ __forceinline__ void tc_gemm_body(const __half* __restrict__ Ap,
                                             const __half* __restrict__ Bp,
                                             const float* __restrict__ bias,
                                             float oscale,
                                             float* __restrict__ C,
                                             __half* __restrict__ F) {
    constexpr int STAGE = 2 * TILE_BY;
    extern __shared__ char smem[];
    const uint32_t sb = smem_u32(smem);
    const int t    = threadIdx.x;
    const int lane = t & 31;
    const int w    = t >> 5;
    const int wm   = (w & 1) * 64;
    const int wn   = (w >> 1) * 64;
    const int m0   = blockIdx.y * 128;
    const int n0   = blockIdx.x * 128;

    const __half* Arow = Ap + (size_t)m0 * D;
    const __half* Brow = Bp + (size_t)n0 * D;

    float acc[4][8][4];
    #pragma unroll
    for (int i = 0; i < 4; i++)
        #pragma unroll
        for (int j = 0; j < 8; j++)
            #pragma unroll
            for (int r = 0; r < 4; r++) acc[i][j][r] = 0.f;

    const int arow  = lane & 15;
    const int akoff = (lane >> 4) * 16;
    const int bn    = (lane & 7) + ((lane >> 4) << 3);
    const int bkoff = ((lane >> 3) & 1) * 16;

    load_stage(sb + 0 * STAGE, Arow, Brow, 0, t);
    load_stage(sb + 1 * STAGE, Arow, Brow, BKG, t);

    int bufc = 0;
    for (int c = 0; c < NITER; c++) {
        if (c + 1 < NITER) { CP_WAIT1(); } else { CP_WAIT0(); }
        __syncthreads();                       // stage c visible; buf (c+2)%3 free

        const uint32_t sbase = sb + bufc * STAGE;
        #pragma unroll
        for (int kk = 0; kk < 2; kk++) {
            const uint32_t kbyte = kk * 32;
            uint32_t ah[4][4];
            #pragma unroll
            for (int mf = 0; mf < 4; mf++) {
                uint32_t ad = sbase + (wm + mf * 16 + arow) * (LDT * 2) + kbyte + akoff;
                ldsm_x4(ah[mf], ad);
            }
            #pragma unroll
            for (int nb = 0; nb < 4; nb++) {
                uint32_t bh4[4];
                uint32_t bd = sbase + TILE_BY + (wn + nb * 16 + bn) * (LDT * 2) + kbyte + bkoff;
                ldsm_x4(bh4, bd);
                #pragma unroll
                for (int mf = 0; mf < 4; mf++)
                    #pragma unroll
                    for (int half = 0; half < 2; half++) {
                        int nf = nb * 2 + half;
                        mma16816h(acc[mf][nf], ah[mf], &bh4[half * 2]);
                    }
            }
        }
        // Issue next-next stage AFTER compute; its buffer was last read at
        // iter c-1 and all warps passed this iter's barrier -> no hazard.
        if (c + 2 < NITER) {
            int bufn = bufc + 2; if (bufn >= 3) bufn -= 3;
            load_stage(sb + bufn * STAGE, Arow, Brow, (c + 2) * BKG, t);
        }
        if (++bufc == 3) bufc = 0;
    }

    // Epilogue
    const int rbase = m0 + wm + (lane >> 2);
    const int cbase = n0 + wn + (lane & 3) * 2;
    #pragma unroll
    for (int mf = 0; mf < 4; mf++) {
        #pragma unroll
        for (int nf = 0; nf < 8; nf++) {
            int col = cbase + nf * 8;
            float2 bv = *(const float2*)(bias + col);
            int r0 = rbase + mf * 16;
            float v0 = (acc[mf][nf][0] + bv.x) * oscale;
            float v1 = (acc[mf][nf][1] + bv.y) * oscale;
            float v2 = (acc[mf][nf][2] + bv.x) * oscale;
            float v3 = (acc[mf][nf][3] + bv.y) * oscale;
            if (MODE == 0) {
                float2 o0 = {v0, v1}, o1 = {v2, v3};
                *(float2*)(C + (size_t)r0 * D + col)       = o0;
                *(float2*)(C + (size_t)(r0 + 8) * D + col) = o1;
            } else {
                *(uint32_t*)(F + (size_t)r0 * D + col) =
                    pack_f16(__float2half_rn(v0), __float2half_rn(v1));
                *(uint32_t*)(F + (size_t)(r0 + 8) * D + col) =
                    pack_f16(__float2half_rn(v2), __float2half_rn(v3));
            }
        }
    }
}

// Q/K/V projections: 1-pass fp16; Q pre-scaled by SCALE_LOG2E
__global__ __launch_bounds__(128, 2) void qkv_tc_gemm(const float* __restrict__ bq,
                                                      const float* __restrict__ bk,
                                                      const float* __restrict__ bv) {
    const int z = blockIdx.z;
    const __half* W = g_wT16 + (size_t)z * D * D;
    const float* bias = (z == 0) ? bq : (z == 1) ? bk : bv;
    __half* Out = (z == 0) ? g_q16 : (z == 1) ? g_k16 : g_v16;
    const float sc = (z == 0) ? SCALE_LOG2E : 1.f;
    tc_gemm_body<2>(g_x16, W, bias, sc, nullptr, Out);
}

// Output projection: 1-pass, fp32 out
__global__ __launch_bounds__(128, 2) void out_tc_gemm(const float* __restrict__ bo,
                                                      float* __restrict__ out) {
    tc_gemm_body<0>(g_c16, g_wT16 + (size_t)3 * D * D, bo, 1.f, out, nullptr);
}

// ---------------------------------------------------------------------------
// Tensor-core flash attention (fp16, causal). Br=Bc=64, 128 threads.
// q pre-scaled, so scores come out of QK^T already in log2 units.
// Software-pipelined: PV(jb-1) fused/interleaved with softmax(jb); exp2 on
// the MUFU pipe. Branchless first iteration (zeroed V tile). 3 K/V buffers.
// ---------------------------------------------------------------------------
constexpr int AT_LDB   = 272;                    // bytes per tile row (128 f16 + pad)
constexpr int AT_TILE  = 64 * AT_LDB;            // 17408 B
constexpr int ATTN_SMEM = 6 * AT_TILE;           // 3 KV buffers (Q reuses tile 0)

__global__ __launch_bounds__(128, 2) void attn_tc_kernel() {
    extern __shared__ char sm8[];
    const uint32_t sb = smem_u32(sm8);

    const int t    = threadIdx.x;
    const int lane = t & 31;
    const int w    = t >> 5;
    const int iq   = (gridDim.x - 1) - blockIdx.x;      // big blocks first
    const int bh   = blockIdx.y;
    const int b    = bh >> 4;
    const int h    = bh & 15;
    const int q0   = iq * 64;
    const int wq   = w * 16;

    // ldmatrix lane offsets
    const int arow  = lane & 15;
    const int akoff = (lane >> 4) * 16;
    const int bn    = (lane & 7) + ((lane >> 4) << 3);
    const int bkoff = ((lane >> 3) & 1) * 16;
    const int vrow  = lane & 15;
    const int vcol  = (lane >> 4) << 3;

    // ---- Load Q into tile 0, hoist to registers ----
    {
        #pragma unroll
        for (int i = 0; i < 8; i++) {
            int idx  = t + 128 * i;
            int row  = idx >> 4;
            int chnk = idx & 15;
            size_t g = (size_t)(b * S + q0 + row) * D + h * DH + chnk * 8;
            cp_async16(sb + row * AT_LDB + chnk * 16, g_q16 + g);
        }
        CP_COMMIT();
        CP_WAIT0();
        __syncthreads();
    }
    uint32_t qhr[8][4];
    #pragma unroll
    for (int kt = 0; kt < 8; kt++) {
        ldsm_x4(qhr[kt], sb + (wq + arow) * AT_LDB + kt * 32 + akoff);
    }
    // Zero V tile of buffer 2 (tile 5): first-iteration dummy PV reads it.
    for (uint32_t i = (uint32_t)t * 16; i < (uint32_t)AT_TILE; i += 128 * 16) {
        *(uint4*)(sm8 + 5 * AT_TILE + i) = make_uint4(0, 0, 0, 0);
    }
    __syncthreads();   // Q reads + zeroing done before KV(0) overwrites tile 0

    // ---- Issue KV(0) -> buf0, KV(1) -> buf1 ----
    #pragma unroll
    for (int i = 0; i < 8; i++) {
        int idx  = t + 128 * i;
        int row  = idx >> 4;
        int chnk = idx & 15;
        size_t g = (size_t)(b * S + row) * D + h * DH + chnk * 8;
        uint32_t so = row * AT_LDB + chnk * 16;
        cp_async16(sb + so, g_k16 + g);
        cp_async16(sb + AT_TILE + so, g_v16 + g);
    }
    CP_COMMIT();
    if (iq >= 1) {
        #pragma unroll
        for (int i = 0; i < 8; i++) {
            int idx  = t + 128 * i;
            int row  = idx >> 4;
            int chnk = idx & 15;
            size_t g = (size_t)(b * S + 64 + row) * D + h * DH + chnk * 8;
            uint32_t so = row * AT_LDB + chnk * 16;
            cp_async16(sb + 2 * AT_TILE + so, g_k16 + g);
            cp_async16(sb + 3 * AT_TILE + so, g_v16 + g);
        }
        CP_COMMIT();
    }

    float o[16][4];
    #pragma unroll
    for (int i = 0; i < 16; i++)
        #pragma unroll
        for (int r = 0; r < 4; r++) o[i][r] = 0.f;
    float m0 = -1e30f, m1 = -1e30f, l0 = 0.f, l1 = 0.f;
    uint32_t pahp[4][4];
    #pragma unroll
    for (int g = 0; g < 4; g++)
        #pragma unroll
        for (int q = 0; q < 4; q++) pahp[g][q] = 0u;   // P(-1) = 0
    float scp0 = 1.f, scp1 = 1.f;

    const int r0g = q0 + wq + (lane >> 2);
    const int r1g = r0g + 8;

    int cur = 0;
    for (int jb = 0; jb <= iq; jb++) {
        const int prv = (cur + 2 >= 3) ? cur - 1 : cur + 2;   // (jb-1)%3 == (jb+2)%3
        if (jb < iq) { CP_WAIT1(); } else { CP_WAIT0(); }
        __syncthreads();                     // KV(jb) visible to all warps

        const uint32_t Kb = sb + (2 * cur) * AT_TILE;
        const uint32_t Vp = sb + (2 * prv + 1) * AT_TILE;     // V(jb-1)
        const int k0 = jb * 64;

        // ---- S = Q K^T (single pass, fp16; already log2-scaled) ----
        float c[8][4];
        #pragma unroll
        for (int j = 0; j < 8; j++)
            #pragma unroll
            for (int r = 0; r < 4; r++) c[j][r] = 0.f;

        #pragma unroll
        for (int kt = 0; kt < 8; kt++) {
            #pragma unroll
            for (int nb = 0; nb < 4; nb++) {
                uint32_t kh4[4];
                ldsm_x4(kh4, Kb + (nb * 16 + bn) * AT_LDB + kt * 32 + bkoff);
                #pragma unroll
                for (int half = 0; half < 2; half++) {
                    int nf = nb * 2 + half;
                    mma16816h(c[nf], qhr[kt], &kh4[half * 2]);
                }
            }
        }

        // ---- causal mask only on the diagonal block (no scaling needed) ----
        if (jb == iq) {
            #pragma unroll
            for (int j = 0; j < 8; j++) {
                int cc = k0 + j * 8 + (lane & 3) * 2;
                #pragma unroll
                for (int r = 0; r < 4; r++) {
                    int col = cc + (r & 1);
                    int row = (r < 2) ? r0g : r1g;
                    if (col > row) c[j][r] = -1e30f;
                }
            }
        }

        // ---- row max + running max ----
        float mx0 = -1e30f, mx1 = -1e30f;
        #pragma unroll
        for (int j = 0; j < 8; j++) {
            mx0 = fmaxf(mx0, fmaxf(c[j][0], c[j][1]));
            mx1 = fmaxf(mx1, fmaxf(c[j][2], c[j][3]));
        }
        mx0 = fmaxf(mx0, __shfl_xor_sync(0xffffffffu, mx0, 1));
        mx0 = fmaxf(mx0, __shfl_xor_sync(0xffffffffu, mx0, 2));
        mx1 = fmaxf(mx1, __shfl_xor_sync(0xffffffffu, mx1, 1));
        mx1 = fmaxf(mx1, __shfl_xor_sync(0xffffffffu, mx1, 2));
        float mn0 = fmaxf(m0, mx0), mn1 = fmaxf(m1, mx1);
        float sc0 = exp2_mufu(m0 - mn0), sc1 = exp2_mufu(m1 - mn1);
        m0 = mn0; m1 = mn1;

        // ---- rescale O by PREVIOUS sc (before adding PV(jb-1)) ----
        #pragma unroll
        for (int nf = 0; nf < 16; nf++) {
            o[nf][0] *= scp0; o[nf][1] *= scp0;
            o[nf][2] *= scp1; o[nf][3] *= scp1;
        }

        // ---- FUSED: PV(jb-1) [tensor] interleaved with exp2 [MUFU] ----
        float ls0 = 0.f, ls1 = 0.f;
        uint32_t pah[4][4];
        #pragma unroll
        for (int g = 0; g < 4; g++) {
            // tensor: PV(jb-1) row-group g
            #pragma unroll
            for (int vb = 0; vb < 8; vb++) {
                uint32_t vh4[4];
                ldsm_x4_t(vh4, Vp + (g * 16 + vrow) * AT_LDB + (vb * 16 + vcol) * 2);
                #pragma unroll
                for (int half = 0; half < 2; half++) {
                    int nf = vb * 2 + half;
                    mma16816h(o[nf], pahp[g], &vh4[half * 2]);
                }
            }
            // scalar/MUFU: exp2 + partial sums + pack for j = 2g, 2g+1
            #pragma unroll
            for (int jj = 0; jj < 2; jj++) {
                int j = 2 * g + jj;
                c[j][0] = exp2_mufu(c[j][0] - mn0);
                c[j][1] = exp2_mufu(c[j][1] - mn0);
                c[j][2] = exp2_mufu(c[j][2] - mn1);
                c[j][3] = exp2_mufu(c[j][3] - mn1);
                ls0 += c[j][0] + c[j][1];
                ls1 += c[j][2] + c[j][3];
            }
            #pragma unroll
            for (int q = 0; q < 4; q++) {
                int j = 2 * g + (q >> 1);
                int e = (q & 1) * 2;
                pah[g][q] = pack_f16(__float2half_rn(c[j][e]),
                                     __float2half_rn(c[j][e + 1]));
            }
        }

        // ---- finish softmax stats ----
        ls0 += __shfl_xor_sync(0xffffffffu, ls0, 1);
        ls0 += __shfl_xor_sync(0xffffffffu, ls0, 2);
        ls1 += __shfl_xor_sync(0xffffffffu, ls1, 1);
        ls1 += __shfl_xor_sync(0xffffffffu, ls1, 2);
        l0 = l0 * sc0 + ls0;
        l1 = l1 * sc1 + ls1;

        // carry P and sc to next iteration
        #pragma unroll
        for (int g = 0; g < 4; g++)
            #pragma unroll
            for (int q = 0; q < 4; q++) pahp[g][q] = pah[g][q];
        scp0 = sc0; scp1 = sc1;

        __syncthreads();                     // everyone done with V(jb-1) buffer
        if (jb + 2 <= iq) {                  // load KV(jb+2) into buffer prv
            const int kn = (jb + 2) * 64;
            const uint32_t buf = sb + (2 * prv) * AT_TILE;
            #pragma unroll
            for (int i = 0; i < 8; i++) {
                int idx  = t + 128 * i;
                int row  = idx >> 4;
                int chnk = idx & 15;
                size_t g = (size_t)(b * S + kn + row) * D + h * DH + chnk * 8;
                uint32_t so = row * AT_LDB + chnk * 16;
                cp_async16(buf + so, g_k16 + g);
                cp_async16(buf + AT_TILE + so, g_v16 + g);
            }
            CP_COMMIT();
        }
        cur = (cur + 1 >= 3) ? 0 : cur + 1;
    }

    // ---- epilogue: final rescale + PV(iq), then normalize and store ----
    {
        const int curv = iq % 3;
        const uint32_t Vl = sb + (2 * curv + 1) * AT_TILE;
        #pragma unroll
        for (int nf = 0; nf < 16; nf++) {
            o[nf][0] *= scp0; o[nf][1] *= scp0;
            o[nf][2] *= scp1; o[nf][3] *= scp1;
        }
        #pragma unroll
        for (int g = 0; g < 4; g++) {
            #pragma unroll
            for (int vb = 0; vb < 8; vb++) {
                uint32_t vh4[4];
                ldsm_x4_t(vh4, Vl + (g * 16 + vrow) * AT_LDB + (vb * 16 + vcol) * 2);
                #pragma unroll
                for (int half = 0; half < 2; half++) {
                    int nf = vb * 2 + half;
                    mma16816h(o[nf], pahp[g], &vh4[half * 2]);
                }
            }
        }
    }

    const float inv0 = 1.f / l0, inv1 = 1.f / l1;
    const int colb = h * DH + (lane & 3) * 2;
    #pragma unroll
    for (int nf = 0; nf < 16; nf++) {
        int col = colb + nf * 8;
        size_t g0 = (size_t)(b * S + r0g) * D + col;
        size_t g1 = (size_t)(b * S + r1g) * D + col;
        *(uint32_t*)(g_c16 + g0) =
            pack_f16(__float2half_rn(o[nf][0] * inv0), __float2half_rn(o[nf][1] * inv0));
        *(uint32_t*)(g_c16 + g1) =
            pack_f16(__float2half_rn(o[nf][2] * inv1), __float2half_rn(o[nf][3] * inv1));
    }
}

// ---------------------------------------------------------------------------
extern "C" void kernel_launch(void* const* d_in, const int* in_sizes, int n_in,
                              void* d_out, int out_size)
{
    const float* X  = (const float*)d_in[0];
    const float* Wq = (const float*)d_in[1];
    const float* bq = (const float*)d_in[2];
    const float* Wk = (const float*)d_in[3];
    const float* bk = (const float*)d_in[4];
    const float* Wv = (const float*)d_in[5];
    const float* bv = (const float*)d_in[6];
    const float* Wo = (const float*)d_in[7];
    const float* bo = (const float*)d_in[8];
    float* out = (float*)d_out;

    cudaFuncSetAttribute(attn_tc_kernel, cudaFuncAttributeMaxDynamicSharedMemorySize, ATTN_SMEM);
    cudaFuncSetAttribute(qkv_tc_gemm, cudaFuncAttributeMaxDynamicSharedMemorySize, GEMM_SMEM2);
    cudaFuncSetAttribute(out_tc_gemm, cudaFuncAttributeMaxDynamicSharedMemorySize, GEMM_SMEM2);

    conv_x_kernel<<<(M * D / 4) / 256, 256>>>((const float4*)X);
    wsplit_kernel<<<dim3(D / 32, D / 32, 4), 256>>>(Wq, Wk, Wv, Wo);
    qkv_tc_gemm<<<dim3(D / 128, M / 128, 3), 128, GEMM_SMEM2>>>(bq, bk, bv);
    attn_tc_kernel<<<dim3(S / 64, B * H), 128, ATTN_SMEM>>>();
    out_tc_gemm<<<dim3(D / 128, M / 128), 128, GEMM_SMEM2>>>(bo, out);
}